// round 14
// baseline (speedup 1.0000x reference)
#include <cuda_runtime.h>

#define NV 4096          // nodes per graph
#define BATCH 32         // batch size == warp width
#define NE 524288        // edges per graph
#define BN (NV * BATCH)  // 131072
#define CAP 256          // fixed bin capacity (max degree ~185 << 256 here)
#define NB 64            // build blocks
#define EPB (NE / NB)    // 8192 edges per build block
#define NPREP 128        // prep blocks
#define SPLIT 4          // warps cooperating on one node's edge list

// Node state, transposed [node][batch]: one node = one 128B line.
__device__ float g_xt[BN];
__device__ float g_fxt[BN];
__device__ float g_mut[BN];    // atomic accumulation
__device__ float g_epst[BN];
__device__ float g_dxa[BN];    // atomic accumulation

// Degree counters: [0..NV) = per-dst, [NV..2NV) = per-src.
// Zero-initialized at load; reset by k_gather_dx tail each call (replay-safe).
__device__ unsigned g_cnt[2 * NV];
__device__ unsigned g_done1[NV];   // mu-pass arrival counters (zeroed by prep)
__device__ unsigned g_done2[NV];   // dx-pass arrival counters (zeroed by prep)

// Fixed-capacity binned adjacency: bin b occupies [b*CAP, b*CAP + cnt[b]).
__device__ int2 g_csr_dst[NV * CAP];   // grouped by dst: {src*32, bits(w)}
__device__ int2 g_csr_src[NV * CAP];   // grouped by src: {dst*32, bits(w)}

// K1: fused prep (blocks 0..NPREP-1) + binned CSR build (blocks NPREP..NPREP+NB-1).
// Prep: transpose x -> xt[N,B], tanh, zero accumulators + done counters.
// Build: smem histograms -> one global reserve atomic per nonzero bin -> place.
// g_cnt starts zero (static init on call 1; reset by gather_dx on later calls).
__global__ void __launch_bounds__(1024) k_prep_build(const float* __restrict__ x,
                                                     const int* __restrict__ esrc,
                                                     const int* __restrict__ edst,
                                                     const float* __restrict__ ew) {
    __shared__ unsigned sh[2 * NV];   // build: hd/hs; prep: reuses as transpose tile
    int t = threadIdx.x;

    if (blockIdx.x < NPREP) {
        // ---------- prep ----------
        float* tile = (float*)sh;     // 32x33 floats
        int tx = t & 31, ty = t >> 5, bx = blockIdx.x;
        tile[ty * 33 + tx] = x[ty * NV + bx * 32 + tx];
        int gidx = bx * 1024 + t;     // NPREP*1024 == BN
        g_mut[gidx] = 0.0f;
        g_dxa[gidx] = 0.0f;
        if (bx < 4) { g_done1[bx * 1024 + t] = 0u; g_done2[bx * 1024 + t] = 0u; }
        __syncthreads();
        int idx = (bx * 32 + ty) * BATCH + tx;
        float v = tile[tx * 33 + ty];
        g_xt[idx]  = v;
        g_fxt[idx] = tanhf(v);
        return;
    }

    // ---------- build ----------
    unsigned* hd = sh;        // dst histogram -> cursor
    unsigned* hs = sh + NV;   // src histogram -> cursor
    int e0 = (blockIdx.x - NPREP) * EPB;

    #pragma unroll
    for (int i = t; i < NV; i += 1024) { hd[i] = 0u; hs[i] = 0u; }
    __syncthreads();

    for (int i = t; i < EPB; i += 1024) {
        atomicAdd(&hd[edst[e0 + i]], 1u);
        atomicAdd(&hs[esrc[e0 + i]], 1u);
    }
    __syncthreads();

    for (int i = t; i < NV; i += 1024) {
        unsigned c = hd[i];
        hd[i] = c ? atomicAdd(&g_cnt[i], c) : 0u;
        c = hs[i];
        hs[i] = c ? atomicAdd(&g_cnt[NV + i], c) : 0u;
    }
    __syncthreads();

    for (int i = t; i < EPB; i += 1024) {
        int e = e0 + i;
        int s = esrc[e], d = edst[e];
        int wb = __float_as_int(ew[e]);
        unsigned p = atomicAdd(&hd[d], 1u);
        g_csr_dst[d * CAP + p] = make_int2(s * 32, wb);
        unsigned q = atomicAdd(&hs[s], 1u);
        g_csr_src[s * CAP + q] = make_int2(d * 32, wb);
    }
}

// Gather body: SPLIT warps per node, 8-edge chunks round-robin by chunk index.
__device__ __forceinline__ float gather_part(const int2* __restrict__ bin,
                                             unsigned n, int w, int lane,
                                             const float* __restrict__ src_arr) {
    float a0 = 0.f, a1 = 0.f, a2 = 0.f, a3 = 0.f;
    #pragma unroll 2
    for (unsigned base = w * 8; base + 8 <= n; base += SPLIT * 8) {
        const int4* q = (const int4*)(bin + base);
        int4 q0 = __ldg(q + 0), q1 = __ldg(q + 1);
        int4 q2 = __ldg(q + 2), q3 = __ldg(q + 3);
        a0 = fmaf(__int_as_float(q0.y), __ldg(&src_arr[q0.x + lane]), a0);
        a1 = fmaf(__int_as_float(q0.w), __ldg(&src_arr[q0.z + lane]), a1);
        a2 = fmaf(__int_as_float(q1.y), __ldg(&src_arr[q1.x + lane]), a2);
        a3 = fmaf(__int_as_float(q1.w), __ldg(&src_arr[q1.z + lane]), a3);
        a0 = fmaf(__int_as_float(q2.y), __ldg(&src_arr[q2.x + lane]), a0);
        a1 = fmaf(__int_as_float(q2.w), __ldg(&src_arr[q2.z + lane]), a1);
        a2 = fmaf(__int_as_float(q3.y), __ldg(&src_arr[q3.x + lane]), a2);
        a3 = fmaf(__int_as_float(q3.w), __ldg(&src_arr[q3.z + lane]), a3);
    }
    if (w == (int)((n >> 3) & (SPLIT - 1))) {     // remainder chunk owner
        for (unsigned i = n & ~7u; i < n; ++i) {
            int2 p = __ldg(bin + i);
            a0 = fmaf(__int_as_float(p.y), __ldg(&src_arr[p.x + lane]), a0);
        }
    }
    return (a0 + a1) + (a2 + a3);
}

// K2: mu partials; node's last-arriving warp computes eps = x - mu and stores mu row.
__global__ void k_gather_mu(float* __restrict__ out) {
    int W = (blockIdx.x * blockDim.x + threadIdx.x) >> 5;
    int lane = threadIdx.x & 31;
    int node = W >> 2, w = W & (SPLIT - 1);
    unsigned n = g_cnt[node];
    float s = gather_part(g_csr_dst + node * CAP, n, w, lane, g_fxt);
    int idx = node * BATCH + lane;
    atomicAdd(&g_mut[idx], s);
    __threadfence();
    unsigned old = 0;
    if (lane == 0) old = atomicAdd(&g_done1[node], 1u);
    old = __shfl_sync(0xffffffffu, old, 0);
    if (old == SPLIT - 1) {
        __threadfence();
        float mu = g_mut[idx];          // all partials visible
        g_epst[idx] = g_xt[idx] - mu;
        out[lane * NV + node] = mu;     // output row 0: [B, N]
    }
}

// K3: dxa partials; last warp computes dx = -eps + (1-fx^2)*dxa, stores dx row,
// and resets g_cnt for the next invocation (replay-safe).
__global__ void k_gather_dx(float* __restrict__ out) {
    int W = (blockIdx.x * blockDim.x + threadIdx.x) >> 5;
    int lane = threadIdx.x & 31;
    int node = W >> 2, w = W & (SPLIT - 1);
    unsigned n = g_cnt[NV + node];
    float s = gather_part(g_csr_src + node * CAP, n, w, lane, g_epst);
    int idx = node * BATCH + lane;
    atomicAdd(&g_dxa[idx], s);
    __threadfence();
    unsigned old = 0;
    if (lane == 0) old = atomicAdd(&g_done2[node], 1u);
    old = __shfl_sync(0xffffffffu, old, 0);
    if (old == SPLIT - 1) {
        __threadfence();
        float acc = g_dxa[idx];
        float fx  = g_fxt[idx];
        float eps = g_epst[idx];
        out[BN + lane * NV + node] = fmaf(1.0f - fx * fx, acc, -eps);
        if (lane == 0) { g_cnt[node] = 0u; g_cnt[NV + node] = 0u; }
    }
}

extern "C" void kernel_launch(void* const* d_in, const int* in_sizes, int n_in,
                              void* d_out, int out_size) {
    const float* x   = (const float*)d_in[0];
    const float* w   = (const float*)d_in[1];
    const int*   src = (const int*)d_in[2];
    const int*   dst = (const int*)d_in[3];
    float* out = (float*)d_out;

    k_prep_build<<<NPREP + NB, 1024>>>(x, src, dst, w);
    k_gather_mu<<<NV * SPLIT * 32 / 256, 256>>>(out);
    k_gather_dx<<<NV * SPLIT * 32 / 256, 256>>>(out);
}

// round 16
// speedup vs baseline: 1.2426x; 1.2426x over previous
#include <cuda_runtime.h>

#define NV 4096          // nodes per graph
#define BATCH 32         // batch size == warp width
#define NE 524288        // edges per graph
#define BN (NV * BATCH)  // 131072
#define CAP 256          // fixed bin capacity (max degree ~185 << 256 here)
#define NBH 64           // histogram/place blocks
#define EPBH (NE / NBH)  // 8192 edges per block
#define NPREP 128        // prep blocks
#define SPLIT 4          // warps cooperating on one node's edge list

// Node state, transposed [node][batch]: one node = one 128B line.
__device__ float g_xt[BN];
__device__ float g_fxt[BN];
__device__ float g_epst[BN];

// Degree totals: [0..NV) per-dst, [NV..2NV) per-src. Overwritten by k_scan.
__device__ unsigned g_cnt[2 * NV];
// Per-block histograms / offsets, block-major: g_bh[k*(2NV) + bin].
__device__ unsigned g_bh[NBH * 2 * NV];
// Fixed-capacity binned adjacency: bin b occupies [b*CAP, b*CAP + cnt[b]).
__device__ int2 g_csr_dst[NV * CAP];   // grouped by dst: {src*32, bits(w)}
__device__ int2 g_csr_src[NV * CAP];   // grouped by src: {dst*32, bits(w)}

// K1: fused prep (blocks 0..NPREP-1) + per-block histograms (NPREP..NPREP+NBH-1).
// These halves touch disjoint state and have no ordering dependency.
__global__ void __launch_bounds__(1024) k_prep_hist(const float* __restrict__ x,
                                                    const int* __restrict__ esrc,
                                                    const int* __restrict__ edst) {
    __shared__ unsigned sh[2 * NV];   // hist bins; prep reuses as transpose tile
    int t = threadIdx.x;

    if (blockIdx.x < NPREP) {
        // ---- prep: transpose x -> xt[N,B], tanh ----
        float* tile = (float*)sh;     // 32x33 floats
        int tx = t & 31, ty = t >> 5, bx = blockIdx.x;
        tile[ty * 33 + tx] = x[ty * NV + bx * 32 + tx];
        __syncthreads();
        int idx = (bx * 32 + ty) * BATCH + tx;
        float v = tile[tx * 33 + ty];
        g_xt[idx]  = v;
        g_fxt[idx] = tanhf(v);
        return;
    }

    // ---- histogram: smem counts -> coalesced row write ----
    int k = blockIdx.x - NPREP;
    int e0 = k * EPBH;
    #pragma unroll
    for (int i = t; i < 2 * NV; i += 1024) sh[i] = 0u;
    __syncthreads();
    for (int i = t; i < EPBH; i += 1024) {
        atomicAdd(&sh[edst[e0 + i]], 1u);
        atomicAdd(&sh[NV + esrc[e0 + i]], 1u);
    }
    __syncthreads();
    unsigned* row = g_bh + k * (2 * NV);
    #pragma unroll
    for (int i = t; i < 2 * NV; i += 1024) row[i] = sh[i];
}

// K2: per-bin prefix over the NBH blocks (no atomics). One thread per bin.
// Converts g_bh counts -> per-(block,bin) exclusive base offsets; totals -> g_cnt.
__global__ void k_scan() {
    int b = blockIdx.x * blockDim.x + threadIdx.x;   // 0 .. 2*NV-1
    unsigned v[NBH];
    #pragma unroll
    for (int k = 0; k < NBH; ++k) v[k] = g_bh[k * (2 * NV) + b];   // independent, coalesced
    unsigned run = 0;
    #pragma unroll
    for (int k = 0; k < NBH; ++k) { unsigned c = v[k]; v[k] = run; run += c; }
    #pragma unroll
    for (int k = 0; k < NBH; ++k) g_bh[k * (2 * NV) + b] = v[k];
    g_cnt[b] = run;
}

// K3: place edges into both binned adjacencies using smem cursors seeded from
// this block's offset row. Only smem atomics; global stores are plain.
__global__ void __launch_bounds__(1024) k_place(const int* __restrict__ esrc,
                                                const int* __restrict__ edst,
                                                const float* __restrict__ ew) {
    __shared__ unsigned cur[2 * NV];
    int t = threadIdx.x;
    int k = blockIdx.x;
    const unsigned* row = g_bh + k * (2 * NV);
    #pragma unroll
    for (int i = t; i < 2 * NV; i += 1024) cur[i] = row[i];
    __syncthreads();
    int e0 = k * EPBH;
    for (int i = t; i < EPBH; i += 1024) {
        int e = e0 + i;
        int s = esrc[e], d = edst[e];
        int wb = __float_as_int(ew[e]);
        unsigned p = atomicAdd(&cur[d], 1u);
        g_csr_dst[d * CAP + p] = make_int2(s * 32, wb);
        unsigned q = atomicAdd(&cur[NV + s], 1u);
        g_csr_src[s * CAP + q] = make_int2(d * 32, wb);
    }
}

// Gather body: SPLIT warps per node, 8-edge chunks round-robin by chunk index.
__device__ __forceinline__ float gather_part(const int2* __restrict__ bin,
                                             unsigned n, int w, int lane,
                                             const float* __restrict__ src_arr) {
    float a0 = 0.f, a1 = 0.f, a2 = 0.f, a3 = 0.f;
    #pragma unroll 2
    for (unsigned base = w * 8; base + 8 <= n; base += SPLIT * 8) {
        const int4* q = (const int4*)(bin + base);
        int4 q0 = __ldg(q + 0), q1 = __ldg(q + 1);
        int4 q2 = __ldg(q + 2), q3 = __ldg(q + 3);
        a0 = fmaf(__int_as_float(q0.y), __ldg(&src_arr[q0.x + lane]), a0);
        a1 = fmaf(__int_as_float(q0.w), __ldg(&src_arr[q0.z + lane]), a1);
        a2 = fmaf(__int_as_float(q1.y), __ldg(&src_arr[q1.x + lane]), a2);
        a3 = fmaf(__int_as_float(q1.w), __ldg(&src_arr[q1.z + lane]), a3);
        a0 = fmaf(__int_as_float(q2.y), __ldg(&src_arr[q2.x + lane]), a0);
        a1 = fmaf(__int_as_float(q2.w), __ldg(&src_arr[q2.z + lane]), a1);
        a2 = fmaf(__int_as_float(q3.y), __ldg(&src_arr[q3.x + lane]), a2);
        a3 = fmaf(__int_as_float(q3.w), __ldg(&src_arr[q3.z + lane]), a3);
    }
    if (w == (int)((n >> 3) & (SPLIT - 1))) {     // remainder chunk owner
        for (unsigned i = n & ~7u; i < n; ++i) {
            int2 p = __ldg(bin + i);
            a0 = fmaf(__int_as_float(p.y), __ldg(&src_arr[p.x + lane]), a0);
        }
    }
    return (a0 + a1) + (a2 + a3);
}

// K4: mu pass. 256-thread block = 2 nodes x SPLIT warps; smem reduction;
// epilogue warp computes eps = x - mu and stores the mu output row.
__global__ void k_gather_mu(float* __restrict__ out) {
    __shared__ float red[8][32];
    int t = threadIdx.x, lane = t & 31, wid = t >> 5;
    int half = wid >> 2, w = wid & (SPLIT - 1);
    int node = blockIdx.x * 2 + half;
    unsigned n = g_cnt[node];
    red[wid][lane] = gather_part(g_csr_dst + node * CAP, n, w, lane, g_fxt);
    __syncthreads();
    if (w == 0) {
        int b = half * 4;
        float mu = (red[b][lane] + red[b+1][lane]) + (red[b+2][lane] + red[b+3][lane]);
        int idx = node * BATCH + lane;
        g_epst[idx] = g_xt[idx] - mu;
        out[lane * NV + node] = mu;          // output row 0: [B, N]
    }
}

// K5: dx pass. Same shape; epilogue computes dx = -eps + (1-fx^2)*acc.
__global__ void k_gather_dx(float* __restrict__ out) {
    __shared__ float red[8][32];
    int t = threadIdx.x, lane = t & 31, wid = t >> 5;
    int half = wid >> 2, w = wid & (SPLIT - 1);
    int node = blockIdx.x * 2 + half;
    unsigned n = g_cnt[NV + node];
    red[wid][lane] = gather_part(g_csr_src + node * CAP, n, w, lane, g_epst);
    __syncthreads();
    if (w == 0) {
        int b = half * 4;
        float acc = (red[b][lane] + red[b+1][lane]) + (red[b+2][lane] + red[b+3][lane]);
        int idx = node * BATCH + lane;
        float fx  = g_fxt[idx];
        float eps = g_epst[idx];
        out[BN + lane * NV + node] = fmaf(1.0f - fx * fx, acc, -eps);
    }
}

extern "C" void kernel_launch(void* const* d_in, const int* in_sizes, int n_in,
                              void* d_out, int out_size) {
    const float* x   = (const float*)d_in[0];
    const float* w   = (const float*)d_in[1];
    const int*   src = (const int*)d_in[2];
    const int*   dst = (const int*)d_in[3];
    float* out = (float*)d_out;

    k_prep_hist<<<NPREP + NBH, 1024>>>(x, src, dst);
    k_scan<<<2 * NV / 256, 256>>>();
    k_place<<<NBH, 1024>>>(src, dst, w);
    k_gather_mu<<<NV / 2, 256>>>(out);
    k_gather_dx<<<NV / 2, 256>>>(out);
}